// round 1
// baseline (speedup 1.0000x reference)
#include <cuda_runtime.h>
#include <cuda_bf16.h>
#include <cstdint>

// ExpandHarmonics: each input reflection i expands into n_max(i) harmonics.
//   g    = gcd(h,k,l); d0 = dHKL*g; n_max = floor(d0/dmin)
//   for n in 1..n_max:  hkl_out=(hkl/g)*n, dHKL_out=d0/n, wav_out=(wav*g)/n, meta copied
// Output buffer (float32): [hkl 3M | dHKL M | wav M | meta DM*M], rows grouped by input row.

#define MAXN   (1 << 20)            // >= 1,000,000 input rows
#define BLK    256
#define MAXB   ((MAXN + BLK - 1) / BLK)   // 4096 blocks max
#define MAXM   (1 << 23)            // 8M output rows max (expected ~2.2M)

__device__ int           g_rowoff[MAXN];      // per-row exclusive offset (local, then global base added implicitly)
__device__ unsigned char g_cnt[MAXN];         // per-row harmonic count (<= 149)
__device__ int           g_blocksum[MAXB + 1];
__device__ int           g_pack[MAXM];        // per-output-row: (src_idx << 8) | harmonic_n

__device__ __forceinline__ int gcd2(int a, int b) {
    while (b) { int t = a % b; a = b; b = t; }
    return a;
}

// ---------------- Pass 1: per-row count + in-block exclusive scan ----------------
__global__ __launch_bounds__(BLK)
void k_count(const int* __restrict__ hkl, const float* __restrict__ dHKL,
             const float* __restrict__ dmin, int N) {
    __shared__ int s[BLK];
    int i = blockIdx.x * BLK + threadIdx.x;
    int cnt = 0;
    if (i < N) {
        int h = hkl[3 * i], k = hkl[3 * i + 1], l = hkl[3 * i + 2];
        int g = gcd2(gcd2(h, k), l);
        float d0 = dHKL[i] * (float)g;
        cnt = (int)floorf(d0 / dmin[0]);        // matches jnp floor_divide (f32 IEEE)
    }
    s[threadIdx.x] = cnt;
    __syncthreads();
    // inclusive Hillis-Steele scan
    #pragma unroll
    for (int off = 1; off < BLK; off <<= 1) {
        int t = (threadIdx.x >= off) ? s[threadIdx.x - off] : 0;
        __syncthreads();
        s[threadIdx.x] += t;
        __syncthreads();
    }
    if (i < N) {
        g_rowoff[i] = s[threadIdx.x] - cnt;     // exclusive within block
        g_cnt[i]    = (unsigned char)cnt;
    }
    if (threadIdx.x == 0) g_blocksum[blockIdx.x] = s[BLK - 1];
}

// ---------------- Pass 2: single-block exclusive scan of block sums ----------------
__global__ __launch_bounds__(1024)
void k_scan_blocks(int B) {
    __shared__ int s[1024];
    int tid = threadIdx.x;
    int ipt = (B + 1023) / 1024;                // <= 4 for our sizes
    int local[8];
    int start = tid * ipt;
    int sum = 0;
    for (int j = 0; j < ipt; j++) {
        int idx = start + j;
        int v = (idx < B) ? g_blocksum[idx] : 0;
        local[j] = sum;                         // exclusive within chunk
        sum += v;
    }
    s[tid] = sum;
    __syncthreads();
    #pragma unroll
    for (int off = 1; off < 1024; off <<= 1) {
        int t = (tid >= off) ? s[tid - off] : 0;
        __syncthreads();
        s[tid] += t;
        __syncthreads();
    }
    int base = s[tid] - sum;                    // exclusive across chunks
    for (int j = 0; j < ipt; j++) {
        int idx = start + j;
        if (idx < B) g_blocksum[idx] = base + local[j];
    }
    if (tid == 1023) g_blocksum[B] = s[1023];   // grand total
}

// ---------------- Pass 3: write per-output-row (idx, n) pack ----------------
__global__ __launch_bounds__(BLK)
void k_pack(int N) {
    int i = blockIdx.x * BLK + threadIdx.x;
    if (i >= N) return;
    int off = g_rowoff[i] + g_blocksum[blockIdx.x];
    int cnt = g_cnt[i];
    int tag = i << 8;
    for (int n = 1; n <= cnt; n++)
        g_pack[off + n - 1] = tag | n;
}

// ---------------- Pass 4: warp-per-output-row scatter ----------------
__global__ __launch_bounds__(256)
void k_scatter(const int* __restrict__ hkl, const float* __restrict__ dHKL,
               const float* __restrict__ wav, const float* __restrict__ meta,
               float* __restrict__ out, int M, int DM) {
    int warp = (blockIdx.x * blockDim.x + threadIdx.x) >> 5;
    int lane = threadIdx.x & 31;
    if (warp >= M) return;
    int pack = g_pack[warp];
    int idx  = pack >> 8;
    int n    = pack & 255;

    // meta: 32 lanes copy DM floats, fully coalesced 128B read + 128B write
    const float* msrc = meta + (long long)idx * DM;
    float*       mdst = out + (long long)(5) * M + (long long)warp * DM; // 3M+M+M = 5M base
    for (int j = lane; j < DM; j += 32)
        mdst[j] = msrc[j];

    if (lane < 5) {
        int h = hkl[3 * idx], k = hkl[3 * idx + 1], l = hkl[3 * idx + 2];
        int g = gcd2(gcd2(h, k), l);
        float fg = (float)g;
        float fn = (float)n;
        if      (lane == 0) out[3 * warp + 0] = (float)((h / g) * n);
        else if (lane == 1) out[3 * warp + 1] = (float)((k / g) * n);
        else if (lane == 2) out[3 * warp + 2] = (float)((l / g) * n);
        else if (lane == 3) out[3 * M + warp] = (dHKL[idx] * fg) / fn;
        else                out[4 * M + warp] = (wav[idx]  * fg) / fn;
    }
}

extern "C" void kernel_launch(void* const* d_in, const int* in_sizes, int n_in,
                              void* d_out, int out_size) {
    const int*   hkl  = (const int*)  d_in[0];
    const float* dHKL = (const float*)d_in[1];
    const float* wav  = (const float*)d_in[2];
    const float* meta = (const float*)d_in[3];
    const float* dmin = (const float*)d_in[4];

    int N  = in_sizes[1];              // dHKL element count == number of rows
    int DM = in_sizes[3] / N;          // metadata feature dim (32)
    int M  = out_size / (5 + DM);      // number of output rows (3+1+1+DM floats each)

    int B = (N + BLK - 1) / BLK;

    k_count<<<B, BLK>>>(hkl, dHKL, dmin, N);
    k_scan_blocks<<<1, 1024>>>(B);
    k_pack<<<B, BLK>>>(N);

    int warpsPerBlock = 256 / 32;      // 8
    int gridScatter = (M + warpsPerBlock - 1) / warpsPerBlock;
    k_scatter<<<gridScatter, 256>>>(hkl, dHKL, wav, meta, (float*)d_out, M, DM);
}

// round 2
// speedup vs baseline: 6.0884x; 6.0884x over previous
#include <cuda_runtime.h>
#include <cuda_bf16.h>
#include <cstdint>

// ExpandHarmonics: each input reflection i expands into n_max(i) harmonics.
// Output buffer (float32): [hkl 3M | dHKL M | wav M | meta DM*M], rows ordered by input row.
//
// R2: hoist all gcd/divide work to the N-scale pass; scatter is pure data movement.

#define MAXN   (1 << 20)
#define BLK    256
#define MAXB   ((MAXN + BLK - 1) / BLK)
#define MAXM   (1 << 23)

__device__ int           g_rowoff[MAXN];     // per-row exclusive offset within block
__device__ unsigned char g_cnt[MAXN];        // per-row harmonic count
__device__ int           g_blocksum[MAXB + 1];
__device__ int           g_pack[MAXM];       // per-output-row: (src_idx << 8) | harmonic_n
__device__ unsigned int  g_hkl0[MAXN];       // packed fundamental indices: h0 | k0<<8 | l0<<16
__device__ float         g_d0[MAXN];         // dHKL * g
__device__ float         g_w0[MAXN];         // wavelength * g

__device__ __forceinline__ int gcd2(int a, int b) {
    while (b) { int t = a % b; a = b; b = t; }
    return a;
}

// ---- Pass 1: per-row count + precompute + in-block scan ----
__global__ __launch_bounds__(BLK)
void k_count(const int* __restrict__ hkl, const float* __restrict__ dHKL,
             const float* __restrict__ wav, const float* __restrict__ dmin, int N) {
    __shared__ int s[BLK];
    int i = blockIdx.x * BLK + threadIdx.x;
    int cnt = 0;
    if (i < N) {
        int h = hkl[3 * i], k = hkl[3 * i + 1], l = hkl[3 * i + 2];
        int g = gcd2(gcd2(h, k), l);
        float fg = (float)g;
        float d0 = dHKL[i] * fg;
        cnt = (int)floorf(d0 / dmin[0]);
        g_hkl0[i] = (unsigned)(h / g) | ((unsigned)(k / g) << 8) | ((unsigned)(l / g) << 16);
        g_d0[i] = d0;
        g_w0[i] = wav[i] * fg;
    }
    s[threadIdx.x] = cnt;
    __syncthreads();
    #pragma unroll
    for (int off = 1; off < BLK; off <<= 1) {
        int t = (threadIdx.x >= off) ? s[threadIdx.x - off] : 0;
        __syncthreads();
        s[threadIdx.x] += t;
        __syncthreads();
    }
    if (i < N) {
        g_rowoff[i] = s[threadIdx.x] - cnt;
        g_cnt[i]    = (unsigned char)cnt;
    }
    if (threadIdx.x == 0) g_blocksum[blockIdx.x] = s[BLK - 1];
}

// ---- Pass 2: single-block exclusive scan of block sums ----
__global__ __launch_bounds__(1024)
void k_scan_blocks(int B) {
    __shared__ int s[1024];
    int tid = threadIdx.x;
    int ipt = (B + 1023) / 1024;
    int local[8];
    int start = tid * ipt;
    int sum = 0;
    for (int j = 0; j < ipt; j++) {
        int idx = start + j;
        int v = (idx < B) ? g_blocksum[idx] : 0;
        local[j] = sum;
        sum += v;
    }
    s[tid] = sum;
    __syncthreads();
    #pragma unroll
    for (int off = 1; off < 1024; off <<= 1) {
        int t = (tid >= off) ? s[tid - off] : 0;
        __syncthreads();
        s[tid] += t;
        __syncthreads();
    }
    int base = s[tid] - sum;
    for (int j = 0; j < ipt; j++) {
        int idx = start + j;
        if (idx < B) g_blocksum[idx] = base + local[j];
    }
    if (tid == 1023) g_blocksum[B] = s[1023];
}

// ---- Pass 3: write per-output-row (idx, n) pack ----
__global__ __launch_bounds__(BLK)
void k_pack(int N) {
    int i = blockIdx.x * BLK + threadIdx.x;
    if (i >= N) return;
    int off = g_rowoff[i] + g_blocksum[blockIdx.x];
    int cnt = g_cnt[i];
    int tag = i << 8;
    for (int n = 1; n <= cnt; n++)
        g_pack[off + n - 1] = tag | n;
}

// ---- Pass 4a: scalar outputs, thread-per-output-row ----
__global__ __launch_bounds__(256)
void k_scalar(float* __restrict__ out, int M) {
    int m = blockIdx.x * 256 + threadIdx.x;
    if (m >= M) return;
    int pack = g_pack[m];
    int idx = pack >> 8;
    int n   = pack & 255;
    unsigned hp = g_hkl0[idx];
    float fn = (float)n;
    out[3 * m + 0] = (float)((int)(hp & 255u) * n);
    out[3 * m + 1] = (float)((int)((hp >> 8) & 255u) * n);
    out[3 * m + 2] = (float)((int)(hp >> 16) * n);
    out[3 * M + m] = g_d0[idx] / fn;
    out[4 * M + m] = g_w0[idx] / fn;
}

// ---- Pass 4b: meta copy, 4 output rows per warp, 8 lanes per row ----
// element mapping e = c + 8*j -> every LDG/STG instruction covers full 32B sectors
__global__ __launch_bounds__(256)
void k_meta(const float* __restrict__ meta, float* __restrict__ out, int M, int DM) {
    int gw   = (blockIdx.x * 256 + threadIdx.x) >> 5;
    int lane = threadIdx.x & 31;
    int r = lane >> 3;          // row within warp group (0..3)
    int c = lane & 7;           // lane within row (0..7)
    int m = gw * 4 + r;
    if (m >= M) return;
    int idx = g_pack[m] >> 8;
    const float* src = meta + (size_t)idx * DM;
    float*       dst = out + (size_t)5 * M + (size_t)m * DM;
    for (int e = c; e < DM; e += 8)
        dst[e] = src[e];
}

extern "C" void kernel_launch(void* const* d_in, const int* in_sizes, int n_in,
                              void* d_out, int out_size) {
    const int*   hkl  = (const int*)  d_in[0];
    const float* dHKL = (const float*)d_in[1];
    const float* wav  = (const float*)d_in[2];
    const float* meta = (const float*)d_in[3];
    const float* dmin = (const float*)d_in[4];

    int N  = in_sizes[1];
    int DM = in_sizes[3] / N;
    int M  = out_size / (5 + DM);

    int B = (N + BLK - 1) / BLK;

    k_count<<<B, BLK>>>(hkl, dHKL, wav, dmin, N);
    k_scan_blocks<<<1, 1024>>>(B);
    k_pack<<<B, BLK>>>(N);

    k_scalar<<<(M + 255) / 256, 256>>>((float*)d_out, M);

    int rowsPerBlock = (256 / 32) * 4;     // 8 warps * 4 rows = 32 rows/block
    k_meta<<<(M + rowsPerBlock - 1) / rowsPerBlock, 256>>>(meta, (float*)d_out, M, DM);
}